// round 8
// baseline (speedup 1.0000x reference)
#include <cuda_runtime.h>
#include <cuda_bf16.h>
#include <cstdint>

// Problem constants (Query2Context_15539191677614)
#define T_LEN 16384
#define J_LEN 64
#define D_LEN 1024
#define GRID1 296          // exactly 2 CTAs/SM on 148+ SMs -> all co-resident
#define QTOT  (T_LEN / 4)  // 4096 row-quads

// Scratch (no cudaMalloc allowed; overwritten every replay -> deterministic)
__device__ float g_partial[GRID1 * D_LEN];  // per-block ctx partials
__device__ float g_bsum[GRID1];             // per-block exp sums

// Monotonic grid barrier state (never reset; safe across graph replays)
__device__ unsigned g_ticket  = 0;
__device__ unsigned g_release = 0;

// ---------------------------------------------------------------------------
// Single persistent kernel.
// Phase 1: fused rowmax/exp + weighted-sum partials (float4 streaming) —
//          identical math/layout to the measured-best R5 k_main.
// Grid barrier (monotonic ticket/release; all 296 blocks co-resident by
//          __launch_bounds__(1024,2), so no deadlock).
// Phase 2: each block computes S and the 3-4 ctx values for its output rows
//          (warp-per-row gather over the L2-hot partials).
// Phase 3: each block streams its output rows with evict-first float4 stores.
// ---------------------------------------------------------------------------
__global__ __launch_bounds__(1024, 2)
void k_fused(const float* __restrict__ h, const float* __restrict__ s,
             float* __restrict__ out) {
    __shared__ float  e_sh[64];        // nrows <= 56
    __shared__ float4 red[4][256];     // 16KB cross-group reduce
    __shared__ float  ctx_sh[8];
    __shared__ float  S_sh;

    const int b     = blockIdx.x;
    const int q0    = (int)(((long long)b       * QTOT) / GRID1);
    const int q1    = (int)(((long long)(b + 1) * QTOT) / GRID1);
    const int nq    = q1 - q0;         // <= 14
    const int t0    = q0 * 4;
    const int nrows = nq * 4;          // <= 56
    const int tid   = threadIdx.x;
    const int w     = tid >> 5;
    const int lane  = tid & 31;

    // ---- Phase 1A: warp-per-row max over J=64 (lane reads float2) ----
    for (int r = w; r < nrows; r += 32) {
        const float2 v = __ldcs(reinterpret_cast<const float2*>(
            s + (size_t)(t0 + r) * J_LEN + lane * 2));
        float m = fmaxf(v.x, v.y);
        #pragma unroll
        for (int off = 16; off > 0; off >>= 1)
            m = fmaxf(m, __shfl_xor_sync(0xFFFFFFFFu, m, off));
        if (lane == 0) e_sh[r] = expf(m);
    }
    __syncthreads();

    // ---- Phase 1B: block exp-sum -> g_bsum[b] (warp 0) ----
    if (w == 0) {
        float bs = 0.0f;
        for (int r = lane; r < nrows; r += 32) bs += e_sh[r];
        #pragma unroll
        for (int off = 16; off > 0; off >>= 1)
            bs += __shfl_xor_sync(0xFFFFFFFFu, bs, off);
        if (lane == 0) g_bsum[b] = bs;
    }

    // ---- Phase 1C: float4 stream over h; 4 rows per iteration ----
    const int g  = tid >> 8;           // row-in-quad 0..3
    const int c4 = tid & 255;          // float4 column 0..255
    float4 acc = make_float4(0.f, 0.f, 0.f, 0.f);
    const float4* __restrict__ hp = reinterpret_cast<const float4*>(
        h + (size_t)(t0 + g) * D_LEN) + c4;
    #pragma unroll 4
    for (int i = 0; i < nq; i++) {
        const float4 v = __ldcs(hp + (size_t)i * D_LEN);
        const float  e = e_sh[4 * i + g];
        acc.x = fmaf(e, v.x, acc.x);
        acc.y = fmaf(e, v.y, acc.y);
        acc.z = fmaf(e, v.z, acc.z);
        acc.w = fmaf(e, v.w, acc.w);
    }
    red[g][c4] = acc;
    __syncthreads();

    {   // reduce across the 4 row-groups; thread owns column k = tid
        const int kc4  = tid >> 2;
        const int comp = tid & 3;
        const float* r0p = reinterpret_cast<const float*>(&red[0][kc4]) + comp;
        g_partial[b * D_LEN + tid] = r0p[0] + r0p[1024] + r0p[2048] + r0p[3072];
    }

    // ---- Grid barrier (monotonic; replay-safe) ----
    __threadfence();
    __syncthreads();
    if (tid == 0) {
        volatile unsigned* rel = &g_release;
        const unsigned gen = *rel;              // read BEFORE arriving
        const unsigned t = atomicAdd(&g_ticket, 1);
        if ((t % GRID1) == (GRID1 - 1)) {
            atomicAdd(&g_release, 1);           // last arriver releases round
        } else {
            while (*rel == gen) { }             // spin (L2 volatile load)
        }
    }
    __syncthreads();
    __threadfence();                            // acquire partials

    // ---- Phase 2: this block's ctx rows + S ----
    const int r0 = (b * D_LEN) / GRID1;
    const int r1 = ((b + 1) * D_LEN) / GRID1;
    const int nr = r1 - r0;                     // 3 or 4

    if (w < nr) {                               // warp w -> output row r0+w
        const int k = r0 + w;
        float a = 0.0f;
        for (int bb = lane; bb < GRID1; bb += 32)
            a += g_partial[bb * D_LEN + k];
        #pragma unroll
        for (int off = 16; off > 0; off >>= 1)
            a += __shfl_xor_sync(0xFFFFFFFFu, a, off);
        if (lane == 0) ctx_sh[w] = a;
    }
    if (w == 4) {                               // warp 4 -> S
        float a = 0.0f;
        for (int bb = lane; bb < GRID1; bb += 32)
            a += g_bsum[bb];
        #pragma unroll
        for (int off = 16; off > 0; off >>= 1)
            a += __shfl_xor_sync(0xFFFFFFFFu, a, off);
        if (lane == 0) S_sh = a;
    }
    __syncthreads();

    // ---- Phase 3: stream output rows (evict-first float4 stores) ----
    for (int r = 0; r < nr; r++) {
        const float v = ctx_sh[r] / S_sh;
        const float4 vv = make_float4(v, v, v, v);
        float4* __restrict__ row =
            reinterpret_cast<float4*>(out) + (size_t)(r0 + r) * (T_LEN / 4);
        #pragma unroll
        for (int j = 0; j < 4; j++)             // 4096 float4 / 1024 thr
            __stcs(row + j * 1024 + tid, vv);
    }
}

// ---------------------------------------------------------------------------
extern "C" void kernel_launch(void* const* d_in, const int* in_sizes, int n_in,
                              void* d_out, int out_size) {
    const float* h = (const float*)d_in[0];   // [1, T, d]
    const float* s = (const float*)d_in[1];   // [T, J]
    float* out = (float*)d_out;               // [d, T]

    k_fused<<<GRID1, 1024>>>(h, s, out);
}